// round 13
// baseline (speedup 1.0000x reference)
#include <cuda_runtime.h>
#include <cuda_fp16.h>
#include <cstdint>

#define T_STEPS 512
#define BATCH   512
#define FEAT    128
#define HID     512
#define TAGS    2
#define NG      2048          // 4*HID
#define K1      640           // FEAT + HID
#define K2      1024          // HID + HID
#define NCTA    256
#define MT      128
#define NT      32
#define NTHREADS 128          // 4 warps, warp tile 32x32
#define NTGROUP 64            // CTAs per M-group

// weights: per k64 block = 32 rows(N) x 128B = 4096 B
#define W1_BLKS 10
#define W2_BLKS 16
#define SM_W2   0                              // 16 * 4096 = 65536 (resident)
#define SM_W1S  65536                          // 3-slot W1 stream ring (12288)
#define SM_AST  (65536 + 12288)                // 77824: 4 warps x 2 slots x 4KB
#define SMEM_BYTES (77824 + 32768)             // 110592 (108KB) -> 2 CTAs/SM

// ------------------------- device globals (scratch) -------------------------
__device__ __half g_Wp1h[NG * K1];       // permuted [n][k], fp16
__device__ __half g_Wp2h[NG * K2];
__device__ float  g_b1[NG];
__device__ float  g_b2[NG];
__device__ __half g_sigh[T_STEPS * BATCH * FEAT];
__device__ __half g_h1[2][BATCH * HID];
__device__ __half g_h2[2][BATCH * HID];
__device__ float  g_c1[BATCH * HID];
__device__ float  g_c2[BATCH * HID];
__device__ unsigned g_bar4[4];
__device__ unsigned g_gen4[4];

// ------------------------------- helpers ------------------------------------
__device__ __forceinline__ float sigm(float x) { return 1.0f / (1.0f + __expf(-x)); }
__device__ __forceinline__ void cp16(uint32_t dst, const void* src) {
    asm volatile("cp.async.cg.shared.global [%0], [%1], 16;\n" :: "r"(dst), "l"(src));
}
#define CPA_COMMIT() asm volatile("cp.async.commit_group;\n")
#define CPA_WAIT1()  asm volatile("cp.async.wait_group 1;\n")
#define CPA_WAIT0()  asm volatile("cp.async.wait_group 0;\n")
#define LDSM4(r0, r1, r2, r3, addr)                                            \
    asm volatile("ldmatrix.sync.aligned.m8n8.x4.shared.b16 {%0,%1,%2,%3}, [%4];" \
        : "=r"(r0), "=r"(r1), "=r"(r2), "=r"(r3) : "r"(addr))

__device__ __forceinline__ unsigned ld_acq(const unsigned* p) {
    unsigned v;
    asm volatile("ld.acquire.gpu.u32 %0, [%1];" : "=r"(v) : "l"(p) : "memory");
    return v;
}

// permuted column index n -> original gate row (gate-interleave of 8)
__device__ __forceinline__ int orig_row(long n) {
    int chunk = (int)(n >> 5), w = (int)(n & 31);
    int q = w >> 3, r = w & 7;
    return q * HID + chunk * 8 + r;
}

// ------------------------------ prep kernel ---------------------------------
__global__ void prep_kernel(const float* __restrict__ signal,
                            const float* __restrict__ Wih1, const float* __restrict__ Whh1,
                            const float* __restrict__ bih1, const float* __restrict__ bhh1,
                            const float* __restrict__ Wih2, const float* __restrict__ Whh2,
                            const float* __restrict__ bih2, const float* __restrict__ bhh2) {
    const long NW1 = (long)NG * K1;
    const long NW2 = (long)NG * K2;
    const long NSIG = (long)T_STEPS * BATCH * FEAT;
    const long NH   = (long)BATCH * HID;
    const long TOT = NW1 + NW2 + 2L * NG + NSIG + 6L * NH;
    for (long i = blockIdx.x * (long)blockDim.x + threadIdx.x; i < TOT;
         i += (long)gridDim.x * blockDim.x) {
        if (i < NW1) {
            long n = i / K1, k = i % K1;
            int o = orig_row(n);
            float v = (k < FEAT) ? Wih1[(long)o * FEAT + k]
                                 : Whh1[(long)o * HID + (k - FEAT)];
            g_Wp1h[i] = __float2half_rn(v);
        } else if (i < NW1 + NW2) {
            long j = i - NW1;
            long n = j / K2, k = j % K2;
            int o = orig_row(n);
            float v = (k < HID) ? Wih2[(long)o * HID + k]
                                : Whh2[(long)o * HID + (k - HID)];
            g_Wp2h[j] = __float2half_rn(v);
        } else if (i < NW1 + NW2 + NG) {
            long n = i - NW1 - NW2;
            int o = orig_row(n);
            g_b1[n] = bih1[o] + bhh1[o];
        } else if (i < NW1 + NW2 + 2L * NG) {
            long n = i - NW1 - NW2 - NG;
            int o = orig_row(n);
            g_b2[n] = bih2[o] + bhh2[o];
        } else if (i < NW1 + NW2 + 2L * NG + NSIG) {
            long j = i - NW1 - NW2 - 2L * NG;
            g_sigh[j] = __float2half_rn(signal[j]);
        } else {
            long j = i - (NW1 + NW2 + 2L * NG + NSIG);
            long seg = j / NH, o = j % NH;
            if      (seg == 0) g_h1[0][o] = __float2half_rn(0.f);
            else if (seg == 1) g_h1[1][o] = __float2half_rn(0.f);
            else if (seg == 2) g_h2[0][o] = __float2half_rn(0.f);
            else if (seg == 3) g_h2[1][o] = __float2half_rn(0.f);
            else if (seg == 4) g_c1[o]    = 0.f;
            else               g_c2[o]    = 0.f;
        }
    }
    if (blockIdx.x == 0 && threadIdx.x < 4) {
        g_bar4[threadIdx.x] = 0u;
        g_gen4[threadIdx.x] = 0u;
    }
}

// --------------------- per-M-group barrier (64 CTAs) -------------------------
__device__ __forceinline__ void group_sync(int mt, unsigned target) {
    __syncthreads();
    if (threadIdx.x == 0) {
        __threadfence();
        unsigned a = atomicAdd(&g_bar4[mt], 1u);
        if (a == NTGROUP - 1u) {
            atomicExch(&g_bar4[mt], 0u);
            __threadfence();
            atomicAdd(&g_gen4[mt], 1u);
        } else {
            while (ld_acq(&g_gen4[mt]) < target) { }
        }
        __threadfence();
    }
    __syncthreads();
}

// --------------------------- A operand sources -------------------------------
struct Src {
    const __half* a0; int lda0; int split;   // k64 chunk idx < split -> a0
    const __half* a1; int lda1;              // otherwise a1
};

__device__ __forceinline__ const __half* srcptr(const Src& s, int idx, int rowA) {
    if (idx < s.split) return s.a0 + (size_t)rowA * s.lda0 + idx * 64;
    return s.a1 + (size_t)rowA * s.lda1 + (idx - s.split) * 64;
}

// A k64 sub-chunk: warp-private slot, lane loads its full 128B row (8 cp16)
__device__ __forceinline__ void put_a(const __half* p, uint32_t dstrow, uint32_t xr) {
    #pragma unroll
    for (int j = 0; j < 8; j++)
        cp16(dstrow + ((uint32_t)(j * 16) ^ xr), p + j * 8);
}

// ---------------------- k64 chunk MMA (W block in smem) ----------------------
__device__ __forceinline__ void mma_chunk(uint32_t ast, const uint32_t ao[2][4],
                                          uint32_t wblk, const uint32_t bo[2][4],
                                          float acc[2][4][4]) {
    #pragma unroll
    for (int kk = 0; kk < 4; kk++) {
        unsigned a[2][4], b[2][4];
        #pragma unroll
        for (int mi = 0; mi < 2; mi++)
            LDSM4(a[mi][0], a[mi][1], a[mi][2], a[mi][3], ast + ao[mi][kk]);
        #pragma unroll
        for (int p2 = 0; p2 < 2; p2++)
            LDSM4(b[p2][0], b[p2][1], b[p2][2], b[p2][3], wblk + bo[p2][kk]);
        #pragma unroll
        for (int mi = 0; mi < 2; mi++)
            #pragma unroll
            for (int j = 0; j < 4; j++) {
                const int p2 = j >> 1, hi = (j & 1) * 2;
                asm volatile(
                    "mma.sync.aligned.m16n8k16.row.col.f32.f16.f16.f32 "
                    "{%0,%1,%2,%3}, {%4,%5,%6,%7}, {%8,%9}, {%0,%1,%2,%3};\n"
                    : "+f"(acc[mi][j][0]), "+f"(acc[mi][j][1]),
                      "+f"(acc[mi][j][2]), "+f"(acc[mi][j][3])
                    : "r"(a[mi][0]), "r"(a[mi][1]), "r"(a[mi][2]), "r"(a[mi][3]),
                      "r"(b[p2][hi]), "r"(b[p2][hi + 1]));
            }
    }
}

__device__ __forceinline__ void zero_acc(float acc[2][4][4]) {
    #pragma unroll
    for (int mi = 0; mi < 2; mi++)
        #pragma unroll
        for (int j = 0; j < 4; j++)
            #pragma unroll
            for (int r = 0; r < 4; r++) acc[mi][j][r] = 0.f;
}

// ------------------- register-local LSTM epilogue ----------------------------
__device__ __forceinline__ void epilogue(const float acc[2][4][4],
                                         const float br[4][2],
                                         float* __restrict__ cbuf,
                                         __half* __restrict__ hout,
                                         int base_row, int colb) {
    #pragma unroll
    for (int mi = 0; mi < 2; mi++) {
        #pragma unroll
        for (int rp = 0; rp < 2; rp++) {
            const int row = base_row + mi * 16 + rp * 8;
            float2 c2 = *(float2*)(cbuf + (size_t)row * HID + colb);
            float hv[2];
            #pragma unroll
            for (int b = 0; b < 2; b++) {
                const int rg = rp * 2 + b;
                float gi = acc[mi][0][rg] + br[0][b];
                float gf = acc[mi][1][rg] + br[1][b];
                float gg = acc[mi][2][rg] + br[2][b];
                float go = acc[mi][3][rg] + br[3][b];
                float c  = b ? c2.y : c2.x;
                float cn = sigm(gf) * c + sigm(gi) * tanhf(gg);
                if (b) c2.y = cn; else c2.x = cn;
                hv[b] = sigm(go) * tanhf(cn);
            }
            *(float2*)(cbuf + (size_t)row * HID + colb) = c2;
            *(__half2*)(hout + (size_t)row * HID + colb) =
                __floats2half2_rn(hv[0], hv[1]);
        }
    }
}

// ----------------------------- output projection -----------------------------
__device__ __forceinline__ void out_calc(int tp, const __half* __restrict__ h2cur,
                                         const float* __restrict__ Wlin,
                                         const float* __restrict__ blin,
                                         float* __restrict__ out, int ct) {
    const int tid = threadIdx.x, lane = tid & 31, wid = tid >> 5;
    if (wid >= 2) return;
    const int b = ct * 2 + wid;                  // 256 CTAs x 2 rows = 512
    const __half* hrow = h2cur + (size_t)b * HID;
    float s0 = 0.f, s1 = 0.f;
    #pragma unroll 8
    for (int k = lane; k < HID; k += 32) {
        float hv = __half2float(__ldcg(hrow + k));
        s0 += hv * __ldg(Wlin + k);
        s1 += hv * __ldg(Wlin + HID + k);
    }
    #pragma unroll
    for (int o = 16; o; o >>= 1) {
        s0 += __shfl_xor_sync(0xffffffffu, s0, o);
        s1 += __shfl_xor_sync(0xffffffffu, s1, o);
    }
    if (lane == 0) {
        out[(size_t)b * (T_STEPS * TAGS) + tp * TAGS + 0] = s0 + blin[0];
        out[(size_t)b * (T_STEPS * TAGS) + tp * TAGS + 1] = s1 + blin[1];
    }
}

// ------------------------------ persistent kernel ----------------------------
__global__ void __launch_bounds__(NTHREADS, 2)
lstm_persistent(const float* __restrict__ Wlin, const float* __restrict__ blin,
                float* __restrict__ out) {
    extern __shared__ char smc[];
    const uint32_t smu = (uint32_t)__cvta_generic_to_shared(smc);
    const int tid = threadIdx.x, w = tid >> 5, lane = tid & 31;
    const int ct = blockIdx.x;
    const int mt = ct >> 6, nt = ct & 63;    // 4 M-groups x 64 N-tiles
    const int m0 = mt * MT, n0 = nt * NT, H0 = nt * 8;

    // ---- preload resident W2 (16 blocks of 32 rows x 128B) ----
    {
        int row = tid >> 2, part = tid & 3;
        uint32_t xr = (uint32_t)((row & 7) * 16);
        uint32_t o0 = (uint32_t)(row * 128) + (((uint32_t)(part * 32)) ^ xr);
        uint32_t o1 = (uint32_t)(row * 128) + (((uint32_t)(part * 32 + 16)) ^ xr);
        const __half* s2 = g_Wp2h + (size_t)(n0 + row) * K2 + part * 16;
        for (int ck = 0; ck < W2_BLKS; ck++) {
            cp16(smu + SM_W2 + ck * 4096 + o0, s2 + ck * 64);
            cp16(smu + SM_W2 + ck * 4096 + o1, s2 + ck * 64 + 8);
        }
        CPA_COMMIT();
        CPA_WAIT0();
        __syncthreads();
    }

    // ---- per-thread biases (gate g, sub-col b) ----
    float b1r[4][2], b2r[4][2];
    #pragma unroll
    for (int g = 0; g < 4; g++)
        #pragma unroll
        for (int b = 0; b < 2; b++) {
            int c = n0 + g * 8 + 2 * (lane & 3) + b;
            b1r[g][b] = g_b1[c];
            b2r[g][b] = g_b2[c];
        }

    // ---- swizzled LDSM B offsets within a 4KB W block [p2][kk] ----
    uint32_t bo[2][4];
    {
        const int brow = ((lane >> 4) & 1) * 8 + (lane & 7);
        const int bcol0 = ((lane >> 3) & 1) * 16;
        #pragma unroll
        for (int p2 = 0; p2 < 2; p2++)
            #pragma unroll
            for (int kk = 0; kk < 4; kk++) {
                int row = p2 * 16 + brow;
                uint32_t col = (uint32_t)(kk * 32 + bcol0);
                bo[p2][kk] = (uint32_t)(row * 128) + (col ^ ((uint32_t)(row & 7) * 16));
            }
    }

    // ---- swizzled LDSM A offsets within a 4KB A slot [mi][kk] ----
    uint32_t ao[2][4];
    {
        const int rr = lane & 15, seg = lane >> 4;
        #pragma unroll
        for (int mi = 0; mi < 2; mi++)
            #pragma unroll
            for (int kk = 0; kk < 4; kk++) {
                int row = mi * 16 + rr;
                uint32_t col = (uint32_t)(kk * 32 + seg * 16);
                ao[mi][kk] = (uint32_t)(row * 128) + (col ^ ((uint32_t)(row & 7) * 16));
            }
    }

    // ---- A stage write-side: lane owns one 128B row ----
    const uint32_t astw = smu + SM_AST + (uint32_t)w * 8192u;      // + slot*4096
    const uint32_t arow = (uint32_t)(lane * 128);
    const uint32_t axr  = (uint32_t)((lane & 7) * 16);
    const int rowA = m0 + w * 32 + lane;

    // ---- W1 stream write-side: warp w loads rows w*8..w*8+7 ----
    const int wrow = w * 8 + (lane >> 2);
    const int wpart = lane & 3;
    const uint32_t wxr = (uint32_t)((wrow & 7) * 16);
    const uint32_t wo0 = (uint32_t)(wrow * 128) + (((uint32_t)(wpart * 32)) ^ wxr);
    const uint32_t wo1 = (uint32_t)(wrow * 128) + (((uint32_t)(wpart * 32 + 16)) ^ wxr);
    const __half* const w1src = g_Wp1h + (size_t)(n0 + wrow) * K1 + wpart * 16;

    const int base_row = m0 + w * 32 + (lane >> 2);
    const int colb = H0 + 2 * (lane & 3);

    float acc[2][4][4];
    unsigned round = 0;

    // ---------------- prologue: A(0) -> h1_0 in g_h1[1] ----------------------
    {
        Src sa;
        sa.a0 = g_sigh;  sa.lda0 = FEAT; sa.split = 2;
        sa.a1 = g_h1[0]; sa.lda1 = HID;           // zeros
        #pragma unroll
        for (int p = 0; p < 2; p++) {             // chunks 0,1: A + W1 blk p
            put_a(srcptr(sa, p, rowA), astw + p * 4096u + arow, axr);
            cp16(smu + SM_W1S + p * 4096u + wo0, w1src + p * 64);
            cp16(smu + SM_W1S + p * 4096u + wo1, w1src + p * 64 + 8);
            CPA_COMMIT();
        }
        zero_acc(acc);
        for (int j = 0; j < W1_BLKS; j++) {
            CPA_WAIT1();
            __syncthreads();
            mma_chunk(astw + (uint32_t)(j & 1) * 4096u, ao,
                      smu + SM_W1S + (uint32_t)(j % 3) * 4096u, bo, acc);
            if (j + 2 < W1_BLKS) {
                put_a(srcptr(sa, j + 2, rowA),
                      astw + (uint32_t)(j & 1) * 4096u + arow, axr);
                cp16(smu + SM_W1S + (uint32_t)((j + 2) % 3) * 4096u + wo0,
                     w1src + (j + 2) * 64);
                cp16(smu + SM_W1S + (uint32_t)((j + 2) % 3) * 4096u + wo1,
                     w1src + (j + 2) * 64 + 8);
            }
            CPA_COMMIT();
        }
        epilogue(acc, b1r, g_c1, g_h1[1], base_row, colb);
        group_sync(mt, ++round);
    }

    // ------------- steady state: region_t = [ B(t) ; A(t+1) ] ----------------
    for (int t = 0; t < T_STEPS; t++) {
        const int cur = (t + 1) & 1, prev = t & 1;
        Src sb;                               // B(t): [h1_t , h2_{t-1}]
        sb.a0 = g_h1[cur]; sb.lda0 = HID; sb.split = 8;
        sb.a1 = g_h2[prev]; sb.lda1 = HID;
        Src sa;                               // A(t+1): [x_{t+1} , h1_t]
        sa.a0 = g_sigh + (size_t)((t + 1) & (T_STEPS - 1)) * BATCH * FEAT;
        sa.lda0 = FEAT; sa.split = 2;
        sa.a1 = g_h1[cur]; sa.lda1 = HID;
        const bool doA = (t + 1 < T_STEPS);

        // kick off pipeline; overlap cold start with out projection
        put_a(srcptr(sb, 0, rowA), astw + arow, axr);
        CPA_COMMIT();
        put_a(srcptr(sb, 1, rowA), astw + 4096u + arow, axr);
        CPA_COMMIT();
        if (t > 0) out_calc(t - 1, g_h2[prev], Wlin, blin, out, ct);

        // ---- B(t): 16 k64 chunks (W2 resident); tail primes A(t+1) ----
        zero_acc(acc);
        for (int j = 0; j < W2_BLKS; j++) {
            CPA_WAIT1();
            __syncwarp();
            mma_chunk(astw + (uint32_t)(j & 1) * 4096u, ao,
                      smu + SM_W2 + (uint32_t)j * 4096u, bo, acc);
            if (j + 2 < W2_BLKS) {
                put_a(srcptr(sb, j + 2, rowA),
                      astw + (uint32_t)(j & 1) * 4096u + arow, axr);
            } else if (doA) {
                const int p = j - 14;         // A chunk 0 at j=14, 1 at j=15
                put_a(srcptr(sa, p, rowA),
                      astw + (uint32_t)(j & 1) * 4096u + arow, axr);
                cp16(smu + SM_W1S + (uint32_t)p * 4096u + wo0, w1src + p * 64);
                cp16(smu + SM_W1S + (uint32_t)p * 4096u + wo1, w1src + p * 64 + 8);
            }
            CPA_COMMIT();
        }
        epilogue(acc, b2r, g_c2, g_h2[cur], base_row, colb);

        // ---- A(t+1): 10 k64 chunks (W1 streamed through 3-slot ring) ----
        if (doA) {
            zero_acc(acc);
            for (int j = 0; j < W1_BLKS; j++) {
                CPA_WAIT1();
                __syncthreads();
                mma_chunk(astw + (uint32_t)(j & 1) * 4096u, ao,
                          smu + SM_W1S + (uint32_t)(j % 3) * 4096u, bo, acc);
                if (j + 2 < W1_BLKS) {
                    put_a(srcptr(sa, j + 2, rowA),
                          astw + (uint32_t)(j & 1) * 4096u + arow, axr);
                    cp16(smu + SM_W1S + (uint32_t)((j + 2) % 3) * 4096u + wo0,
                         w1src + (j + 2) * 64);
                    cp16(smu + SM_W1S + (uint32_t)((j + 2) % 3) * 4096u + wo1,
                         w1src + (j + 2) * 64 + 8);
                }
                CPA_COMMIT();
            }
            epilogue(acc, b1r, g_c1, g_h1[prev], base_row, colb);   // h1_{t+1}
        }
        group_sync(mt, ++round);
    }
    out_calc(T_STEPS - 1, g_h2[0], Wlin, blin, out, ct);
}

// --------------------------------- launcher ----------------------------------
extern "C" void kernel_launch(void* const* d_in, const int* in_sizes, int n_in,
                              void* d_out, int out_size) {
    const float* signal = (const float*)d_in[0];
    const float* Wih1   = (const float*)d_in[1];
    const float* Whh1   = (const float*)d_in[2];
    const float* bih1   = (const float*)d_in[3];
    const float* bhh1   = (const float*)d_in[4];
    const float* Wih2   = (const float*)d_in[5];
    const float* Whh2   = (const float*)d_in[6];
    const float* bih2   = (const float*)d_in[7];
    const float* bhh2   = (const float*)d_in[8];
    const float* Wlin   = (const float*)d_in[9];
    const float* blin   = (const float*)d_in[10];
    float* out = (float*)d_out;

    (void)in_sizes; (void)n_in; (void)out_size;

    cudaFuncSetAttribute(lstm_persistent,
                         cudaFuncAttributeMaxDynamicSharedMemorySize, SMEM_BYTES);

    prep_kernel<<<4096, 256>>>(signal, Wih1, Whh1, bih1, bhh1,
                               Wih2, Whh2, bih2, bhh2);
    lstm_persistent<<<NCTA, NTHREADS, SMEM_BYTES>>>(Wlin, blin, out);
}

// round 14
// speedup vs baseline: 1.8443x; 1.8443x over previous
#include <cuda_runtime.h>
#include <cuda_fp16.h>
#include <cstdint>

#define T_STEPS 512
#define BATCH   512
#define FEAT    128
#define HID     512
#define TAGS    2
#define NG      2048          // 4*HID
#define K1      640           // FEAT + HID
#define K2      1024          // HID + HID
#define NCTA    128
#define MT      128
#define NT      64
#define NTHREADS 256          // 8 warps: 4 M-subgroups x 2 N-halves, tile 32x32
#define NTGROUP 32            // CTAs per M-group

// resident weights: per k64 block = 64 rows(N) x 128B = 8192 B
#define W1_BLKS 8             // h1 part only (orig k=128..639)
#define W2_BLKS 16
#define SM_W1   0
#define SM_W2   (W1_BLKS * 8192)                  // 65536
#define SM_AST  ((W1_BLKS + W2_BLKS) * 8192)      // 196608: pair A stages
#define SMEM_BYTES (SM_AST + 4 * 4 * 2048)        // 229376 (4 pairs x 4 slots x 2KB)

// gemm_x kernel smem
#define GX_W    0                                  // 2 blocks = 16384
#define GX_AST  16384
#define GX_SMEM (16384 + 32768)                    // 49152

// ------------------------- device globals (scratch) -------------------------
__device__ __half g_Wp1h[NG * K1];       // permuted [n][k], fp16
__device__ __half g_Wp2h[NG * K2];
__device__ float  g_b1[NG];
__device__ float  g_b2[NG];
__device__ __half g_sigh[T_STEPS * BATCH * FEAT];
__device__ __half g_h1[2][BATCH * HID];
__device__ __half g_h2[2][BATCH * HID];
__device__ float  g_c1[BATCH * HID];
__device__ float  g_c2[BATCH * HID];
__device__ unsigned g_bar4[4];
__device__ unsigned g_gen4[4];
// precomputed x*W1x^T in per-thread fragment order: [ct][t][tid][32 halves]
__device__ __half g_gx[(size_t)NCTA * T_STEPS * NTHREADS * 32];

// ------------------------------- helpers ------------------------------------
__device__ __forceinline__ float sigm(float x) { return 1.0f / (1.0f + __expf(-x)); }
__device__ __forceinline__ void cp16(uint32_t dst, const void* src) {
    asm volatile("cp.async.cg.shared.global [%0], [%1], 16;\n" :: "r"(dst), "l"(src));
}
#define CPA_COMMIT() asm volatile("cp.async.commit_group;\n")
#define CPA_WAIT2()  asm volatile("cp.async.wait_group 2;\n")
#define CPA_WAIT0()  asm volatile("cp.async.wait_group 0;\n")
#define PBAR(mg)     asm volatile("bar.sync %0, 64;" :: "r"(1 + (mg)) : "memory")
#define LDSM4(r0, r1, r2, r3, addr)                                            \
    asm volatile("ldmatrix.sync.aligned.m8n8.x4.shared.b16 {%0,%1,%2,%3}, [%4];" \
        : "=r"(r0), "=r"(r1), "=r"(r2), "=r"(r3) : "r"(addr))

__device__ __forceinline__ unsigned ld_acq(const unsigned* p) {
    unsigned v;
    asm volatile("ld.acquire.gpu.u32 %0, [%1];" : "=r"(v) : "l"(p) : "memory");
    return v;
}

// permuted column index n -> original gate row (gate-interleave of 8)
__device__ __forceinline__ int orig_row(long n) {
    int chunk = (int)(n >> 5), w = (int)(n & 31);
    int q = w >> 3, r = w & 7;
    return q * HID + chunk * 8 + r;
}

// ------------------------------ prep kernel ---------------------------------
__global__ void prep_kernel(const float* __restrict__ signal,
                            const float* __restrict__ Wih1, const float* __restrict__ Whh1,
                            const float* __restrict__ bih1, const float* __restrict__ bhh1,
                            const float* __restrict__ Wih2, const float* __restrict__ Whh2,
                            const float* __restrict__ bih2, const float* __restrict__ bhh2) {
    const long NW1 = (long)NG * K1;
    const long NW2 = (long)NG * K2;
    const long NSIG = (long)T_STEPS * BATCH * FEAT;
    const long NH   = (long)BATCH * HID;
    const long TOT = NW1 + NW2 + 2L * NG + NSIG + 6L * NH;
    for (long i = blockIdx.x * (long)blockDim.x + threadIdx.x; i < TOT;
         i += (long)gridDim.x * blockDim.x) {
        if (i < NW1) {
            long n = i / K1, k = i % K1;
            int o = orig_row(n);
            float v = (k < FEAT) ? Wih1[(long)o * FEAT + k]
                                 : Whh1[(long)o * HID + (k - FEAT)];
            g_Wp1h[i] = __float2half_rn(v);
        } else if (i < NW1 + NW2) {
            long j = i - NW1;
            long n = j / K2, k = j % K2;
            int o = orig_row(n);
            float v = (k < HID) ? Wih2[(long)o * HID + k]
                                : Whh2[(long)o * HID + (k - HID)];
            g_Wp2h[j] = __float2half_rn(v);
        } else if (i < NW1 + NW2 + NG) {
            long n = i - NW1 - NW2;
            int o = orig_row(n);
            g_b1[n] = bih1[o] + bhh1[o];
        } else if (i < NW1 + NW2 + 2L * NG) {
            long n = i - NW1 - NW2 - NG;
            int o = orig_row(n);
            g_b2[n] = bih2[o] + bhh2[o];
        } else if (i < NW1 + NW2 + 2L * NG + NSIG) {
            long j = i - NW1 - NW2 - 2L * NG;
            g_sigh[j] = __float2half_rn(signal[j]);
        } else {
            long j = i - (NW1 + NW2 + 2L * NG + NSIG);
            long seg = j / NH, o = j % NH;
            if      (seg == 0) g_h1[0][o] = __float2half_rn(0.f);
            else if (seg == 1) g_h1[1][o] = __float2half_rn(0.f);
            else if (seg == 2) g_h2[0][o] = __float2half_rn(0.f);
            else if (seg == 3) g_h2[1][o] = __float2half_rn(0.f);
            else if (seg == 4) g_c1[o]    = 0.f;
            else               g_c2[o]    = 0.f;
        }
    }
    if (blockIdx.x == 0 && threadIdx.x < 4) {
        g_bar4[threadIdx.x] = 0u;
        g_gen4[threadIdx.x] = 0u;
    }
}

// --------------------- per-M-group barrier (32 CTAs) -------------------------
__device__ __forceinline__ void group_sync(int mt, unsigned target) {
    __syncthreads();
    if (threadIdx.x == 0) {
        __threadfence();
        unsigned a = atomicAdd(&g_bar4[mt], 1u);
        if (a == NTGROUP - 1u) {
            atomicExch(&g_bar4[mt], 0u);
            __threadfence();
            atomicAdd(&g_gen4[mt], 1u);
        } else {
            while (ld_acq(&g_gen4[mt]) < target) { }
        }
        __threadfence();
    }
    __syncthreads();
}

// --------------------------- pair A staging ----------------------------------
struct Src {
    const __half* a0; int lda0; int split;   // k32 sub-chunk idx < split -> a0
    const __half* a1; int lda1;              // otherwise a1
};

__device__ __forceinline__ void issue_sub(const Src& s, int idx, int rowA, int coff,
                                          uint32_t d0, uint32_t d1) {
    const __half* p;
    if (idx < s.split) p = s.a0 + (size_t)rowA * s.lda0 + idx * 32 + coff;
    else               p = s.a1 + (size_t)rowA * s.lda1 + (idx - s.split) * 32 + coff;
    cp16(d0, p);
    cp16(d1, p + 8);
    CPA_COMMIT();
}

// ------------------------ fragment load / MMA --------------------------------
struct Frags { unsigned a[2][2][4]; unsigned b[2][2][4]; };  // [kk][mi/p2][4]

__device__ __forceinline__ void load_frags(Frags& f, uint32_t stg,
                                           const uint32_t a_off[2][2],
                                           uint32_t wphase, int k16g,
                                           const uint32_t bo_sw[2][4]) {
    #pragma unroll
    for (int kk = 0; kk < 2; kk++) {
        #pragma unroll
        for (int mi = 0; mi < 2; mi++)
            LDSM4(f.a[kk][mi][0], f.a[kk][mi][1], f.a[kk][mi][2], f.a[kk][mi][3],
                  stg + a_off[mi][kk]);
        const int kg = k16g + kk;
        const uint32_t wblk = wphase + (uint32_t)(kg >> 2) * 8192u;
        const int k4 = kg & 3;
        #pragma unroll
        for (int p2 = 0; p2 < 2; p2++)
            LDSM4(f.b[kk][p2][0], f.b[kk][p2][1], f.b[kk][p2][2], f.b[kk][p2][3],
                  wblk + bo_sw[p2][k4]);
    }
}

__device__ __forceinline__ void mma_frags(const Frags& f, float acc[2][4][4]) {
    #pragma unroll
    for (int kk = 0; kk < 2; kk++)
        #pragma unroll
        for (int mi = 0; mi < 2; mi++)
            #pragma unroll
            for (int j = 0; j < 4; j++) {
                const int p2 = j >> 1, hi = (j & 1) * 2;
                asm volatile(
                    "mma.sync.aligned.m16n8k16.row.col.f32.f16.f16.f32 "
                    "{%0,%1,%2,%3}, {%4,%5,%6,%7}, {%8,%9}, {%0,%1,%2,%3};\n"
                    : "+f"(acc[mi][j][0]), "+f"(acc[mi][j][1]),
                      "+f"(acc[mi][j][2]), "+f"(acc[mi][j][3])
                    : "r"(f.a[kk][mi][0]), "r"(f.a[kk][mi][1]),
                      "r"(f.a[kk][mi][2]), "r"(f.a[kk][mi][3]),
                      "r"(f.b[kk][p2][hi]), "r"(f.b[kk][p2][hi + 1]));
            }
}

__device__ __forceinline__ void zero_acc(float acc[2][4][4]) {
    #pragma unroll
    for (int mi = 0; mi < 2; mi++)
        #pragma unroll
        for (int j = 0; j < 4; j++)
            #pragma unroll
            for (int r = 0; r < 4; r++) acc[mi][j][r] = 0.f;
}

// ------------------- register-local LSTM epilogue ----------------------------
__device__ __forceinline__ void epilogue(const float acc[2][4][4],
                                         const float br[4][2],
                                         float* __restrict__ cbuf,
                                         __half* __restrict__ hout,
                                         int base_row, int colb) {
    #pragma unroll
    for (int mi = 0; mi < 2; mi++) {
        #pragma unroll
        for (int rp = 0; rp < 2; rp++) {
            const int row = base_row + mi * 16 + rp * 8;
            float2 c2 = *(float2*)(cbuf + (size_t)row * HID + colb);
            float hv[2];
            #pragma unroll
            for (int b = 0; b < 2; b++) {
                const int rg = rp * 2 + b;
                float gi = acc[mi][0][rg] + br[0][b];
                float gf = acc[mi][1][rg] + br[1][b];
                float gg = acc[mi][2][rg] + br[2][b];
                float go = acc[mi][3][rg] + br[3][b];
                float c  = b ? c2.y : c2.x;
                float cn = sigm(gf) * c + sigm(gi) * tanhf(gg);
                if (b) c2.y = cn; else c2.x = cn;
                hv[b] = sigm(go) * tanhf(cn);
            }
            *(float2*)(cbuf + (size_t)row * HID + colb) = c2;
            *(__half2*)(hout + (size_t)row * HID + colb) =
                __floats2half2_rn(hv[0], hv[1]);
        }
    }
}

// ----------------------------- output projection -----------------------------
__device__ __forceinline__ void out_calc(int tp, const __half* __restrict__ h2cur,
                                         const float* __restrict__ Wlin,
                                         const float* __restrict__ blin,
                                         float* __restrict__ out, int ct) {
    const int tid = threadIdx.x, lane = tid & 31, wid = tid >> 5;
    if (wid >= 4) return;
    const int b = ct * 4 + wid;
    const __half* hrow = h2cur + (size_t)b * HID;
    float s0 = 0.f, s1 = 0.f;
    #pragma unroll 8
    for (int k = lane; k < HID; k += 32) {
        float hv = __half2float(__ldcg(hrow + k));
        s0 += hv * __ldg(Wlin + k);
        s1 += hv * __ldg(Wlin + HID + k);
    }
    #pragma unroll
    for (int o = 16; o; o >>= 1) {
        s0 += __shfl_xor_sync(0xffffffffu, s0, o);
        s1 += __shfl_xor_sync(0xffffffffu, s1, o);
    }
    if (lane == 0) {
        out[(size_t)b * (T_STEPS * TAGS) + tp * TAGS + 0] = s0 + blin[0];
        out[(size_t)b * (T_STEPS * TAGS) + tp * TAGS + 1] = s1 + blin[1];
    }
}

// ======================= gemm_x: gx = x_t * W1x^T for all t ==================
__global__ void __launch_bounds__(NTHREADS, 1)
gemm_x_kernel() {
    extern __shared__ char smc[];
    const uint32_t smu = (uint32_t)__cvta_generic_to_shared(smc);
    const int tid = threadIdx.x, w = tid >> 5, lane = tid & 31;
    const int mg = w >> 1, nh = w & 1;
    const int ct = blockIdx.x;
    const int mt = ct >> 5, nt = ct & 31;
    const int m0 = mt * MT, n0 = nt * NT;

    // preload W1x (k blocks 0,1 of g_Wp1h)
    {
        int row = tid >> 2, part = tid & 3;
        uint32_t rb = (uint32_t)(row * 128 + part * 32);
        uint32_t o0 = rb;        o0 ^= (o0 >> 3) & 0x70u;
        uint32_t o1 = rb + 16;   o1 ^= (o1 >> 3) & 0x70u;
        const __half* s1 = g_Wp1h + (size_t)(n0 + row) * K1 + part * 16;
        for (int ckk = 0; ckk < 2; ckk++) {
            cp16(smu + GX_W + ckk * 8192 + o0, s1 + ckk * 64);
            cp16(smu + GX_W + ckk * 8192 + o1, s1 + ckk * 64 + 8);
        }
        CPA_COMMIT();
        CPA_WAIT0();
        __syncthreads();
    }

    const uint32_t b_off0 = (uint32_t)(((((lane >> 4) & 1) * 8 + (lane & 7)) * 128)
                                       + ((lane >> 3) & 1) * 16);
    uint32_t bo_sw[2][4];
    #pragma unroll
    for (int p2 = 0; p2 < 2; p2++)
        #pragma unroll
        for (int kk = 0; kk < 4; kk++) {
            uint32_t bo = b_off0 + (uint32_t)((2 * nh + p2) * 2048 + kk * 32);
            bo ^= (bo >> 3) & 0x70u;
            bo_sw[p2][kk] = bo;
        }

    const uint32_t pstage = smu + GX_AST + (uint32_t)mg * 8192u;
    const int pt = nh * 32 + lane;
    const uint32_t wpre = (uint32_t)((pt >> 2) * 128 + ((pt >> 1) & 1) * 64
                                     + (pt & 1) * 32);
    const uint32_t wsw  = ((uint32_t)(pt >> 2) & 7u) << 4;
    const uint32_t wd0  = wpre ^ wsw;
    const uint32_t wd1  = (wpre + 16) ^ wsw;
    const int coff = (lane & 1) * 16;
    const int rowm = m0 + mg * 32 + nh * 16 + (lane >> 1);

    const int rr = lane & 15;
    uint32_t a_off[2][2];
    #pragma unroll
    for (int mi = 0; mi < 2; mi++)
        #pragma unroll
        for (int kk = 0; kk < 2; kk++) {
            uint32_t ap = (uint32_t)(mi * 1024 + (rr >> 1) * 128 + (rr & 1) * 64
                                     + kk * 32 + (lane >> 4) * 16);
            ap ^= ((uint32_t)(rr >> 1) & 7u) << 4;
            a_off[mi][kk] = ap;
        }

    auto issue_x = [&](int c) {
        const int t = c >> 2, s = c & 3;
        const __half* p = g_sigh + ((size_t)t * BATCH + rowm) * FEAT + s * 32 + coff;
        const uint32_t stg = pstage + (uint32_t)(c & 3) * 2048u;
        cp16(stg + wd0, p);
        cp16(stg + wd1, p + 8);
        CPA_COMMIT();
    };

    float acc[2][4][4];
    Frags f;
    issue_x(0); issue_x(1); issue_x(2);
    zero_acc(acc);
    const int NCH = 4 * T_STEPS;
    for (int c = 0; c < NCH; c++) {
        CPA_WAIT2();
        PBAR(mg);
        const uint32_t stg = pstage + (uint32_t)(c & 3) * 2048u;
        load_frags(f, stg, a_off, smu + GX_W, (c & 3) * 2, bo_sw);
        if (c + 3 < NCH) issue_x(c + 3); else CPA_COMMIT();
        mma_frags(f, acc);
        if ((c & 3) == 3) {
            const int t = c >> 2;
            uint4 v[4];
            __half2* hp = (__half2*)v;
            #pragma unroll
            for (int mi = 0; mi < 2; mi++)
                #pragma unroll
                for (int j = 0; j < 4; j++)
                    #pragma unroll
                    for (int r = 0; r < 4; r += 2)
                        hp[((mi * 4 + j) * 4 + r) >> 1] =
                            __floats2half2_rn(acc[mi][j][r], acc[mi][j][r + 1]);
            __half* dst = g_gx + ((size_t)(ct * T_STEPS + t) * NTHREADS + tid) * 32;
            #pragma unroll
            for (int k = 0; k < 4; k++) *((uint4*)(dst + k * 8)) = v[k];
            zero_acc(acc);
        }
    }
}

// ------------------------------ persistent kernel ----------------------------
__global__ void __launch_bounds__(NTHREADS, 1)
lstm_persistent(const float* __restrict__ Wlin, const float* __restrict__ blin,
                float* __restrict__ out) {
    extern __shared__ char smc[];
    const uint32_t smu = (uint32_t)__cvta_generic_to_shared(smc);
    const int tid = threadIdx.x, w = tid >> 5, lane = tid & 31;
    const int mg = w >> 1, nh = w & 1;
    const int ct = blockIdx.x;
    const int mt = ct >> 5, nt = ct & 31;
    const int m0 = mt * MT, n0 = nt * NT, H0 = nt * 16;

    // ---- preload resident W1 h-part (8 blocks: orig k-blocks 2..9) + W2 ----
    {
        int row = tid >> 2, part = tid & 3;
        uint32_t rb = (uint32_t)(row * 128 + part * 32);
        uint32_t o0 = rb;        o0 ^= (o0 >> 3) & 0x70u;
        uint32_t o1 = rb + 16;   o1 ^= (o1 >> 3) & 0x70u;
        const __half* s1 = g_Wp1h + (size_t)(n0 + row) * K1 + part * 16;
        for (int ckk = 0; ckk < W1_BLKS; ckk++) {
            cp16(smu + SM_W1 + ckk * 8192 + o0, s1 + (ckk + 2) * 64);
            cp16(smu + SM_W1 + ckk * 8192 + o1, s1 + (ckk + 2) * 64 + 8);
        }
        const __half* s2 = g_Wp2h + (size_t)(n0 + row) * K2 + part * 16;
        for (int ckk = 0; ckk < W2_BLKS; ckk++) {
            cp16(smu + SM_W2 + ckk * 8192 + o0, s2 + ckk * 64);
            cp16(smu + SM_W2 + ckk * 8192 + o1, s2 + ckk * 64 + 8);
        }
        CPA_COMMIT();
        CPA_WAIT0();
        __syncthreads();
    }

    // ---- per-thread biases in registers (gate g, sub-col b) ----
    float b1r[4][2], b2r[4][2];
    #pragma unroll
    for (int g = 0; g < 4; g++)
        #pragma unroll
        for (int b = 0; b < 2; b++) {
            int c = n0 + nh * 32 + g * 8 + 2 * (lane & 3) + b;
            b1r[g][b] = g_b1[c];
            b2r[g][b] = g_b2[c];
        }

    // ---- swizzled LDSM offsets for B: this warp's two n16 blocks ----
    const uint32_t b_off0 = (uint32_t)(((((lane >> 4) & 1) * 8 + (lane & 7)) * 128)
                                       + ((lane >> 3) & 1) * 16);
    uint32_t bo_sw[2][4];
    #pragma unroll
    for (int p2 = 0; p2 < 2; p2++)
        #pragma unroll
        for (int kk = 0; kk < 4; kk++) {
            uint32_t bo = b_off0 + (uint32_t)((2 * nh + p2) * 2048 + kk * 32);
            bo ^= (bo >> 3) & 0x70u;
            bo_sw[p2][kk] = bo;
        }

    // ---- pair A stage: 4 slots x 2KB ----
    const uint32_t pstage = smu + SM_AST + (uint32_t)mg * 8192u;
    const int pt = nh * 32 + lane;
    const uint32_t wpre = (uint32_t)((pt >> 2) * 128 + ((pt >> 1) & 1) * 64
                                     + (pt & 1) * 32);
    const uint32_t wsw  = ((uint32_t)(pt >> 2) & 7u) << 4;
    const uint32_t wd0  = wpre ^ wsw;
    const uint32_t wd1  = (wpre + 16) ^ wsw;
    const int coff = (lane & 1) * 16;
    const int rowA = m0 + mg * 32 + nh * 16 + (lane >> 1);

    const int rr = lane & 15;
    uint32_t a_off[2][2];
    #pragma unroll
    for (int mi = 0; mi < 2; mi++)
        #pragma unroll
        for (int kk = 0; kk < 2; kk++) {
            uint32_t ap = (uint32_t)(mi * 1024 + (rr >> 1) * 128 + (rr & 1) * 64
                                     + kk * 32 + (lane >> 4) * 16);
            ap ^= ((uint32_t)(rr >> 1) & 7u) << 4;
            a_off[mi][kk] = ap;
        }

    const int base_row = m0 + mg * 32 + (lane >> 2);
    const int colb = H0 + nh * 8 + 2 * (lane & 3);

    float acc[2][4][4];
    Frags f;
    unsigned round = 0;

    auto init_from_gx = [&](const uint4 gxv[4]) {
        const __half2* hp = (const __half2*)gxv;
        #pragma unroll
        for (int mi = 0; mi < 2; mi++)
            #pragma unroll
            for (int j = 0; j < 4; j++)
                #pragma unroll
                for (int r = 0; r < 4; r += 2) {
                    float2 f2 = __half22float2(hp[((mi * 4 + j) * 4 + r) >> 1]);
                    acc[mi][j][r]     = f2.x;
                    acc[mi][j][r + 1] = f2.y;
                }
    };
    auto gx_ptr = [&](int t) {
        return (const uint4*)(g_gx + ((size_t)(ct * T_STEPS + t) * NTHREADS + tid) * 32);
    };

    // ---------------- prologue: A(0) = gx(0) + 0*W1h -> h1_0 in g_h1[1] ------
    {
        Src sa;
        sa.a0 = g_h1[0]; sa.lda0 = HID; sa.split = 16;   // zeros
        sa.a1 = g_h1[0]; sa.lda1 = HID;
        issue_sub(sa, 0, rowA, coff, pstage + wd0, pstage + wd1);
        issue_sub(sa, 1, rowA, coff, pstage + 2048 + wd0, pstage + 2048 + wd1);
        issue_sub(sa, 2, rowA, coff, pstage + 4096 + wd0, pstage + 4096 + wd1);
        uint4 gxv[4];
        const uint4* gp = gx_ptr(0);
        #pragma unroll
        for (int k = 0; k < 4; k++) gxv[k] = __ldcg(gp + k);
        init_from_gx(gxv);
        #pragma unroll 2
        for (int j = 0; j < 16; j++) {
            CPA_WAIT2();
            PBAR(mg);
            const uint32_t stg = pstage + (uint32_t)(j & 3) * 2048u;
            load_frags(f, stg, a_off, smu + SM_W1, j * 2, bo_sw);
            if (j + 3 < 16) {
                const uint32_t ds = pstage + (uint32_t)((j + 3) & 3) * 2048u;
                issue_sub(sa, j + 3, rowA, coff, ds + wd0, ds + wd1);
            } else CPA_COMMIT();
            mma_frags(f, acc);
        }
        epilogue(acc, b1r, g_c1, g_h1[1], base_row, colb);
        group_sync(mt, ++round);
    }

    // ------------- steady state: region_t = [ B(t) ; A(t+1) ] ----------------
    for (int t = 0; t < T_STEPS; t++) {
        const int cur = (t + 1) & 1, prev = t & 1;
        Src sb;                               // B(t): [h1_t , h2_{t-1}]
        sb.a0 = g_h1[cur]; sb.lda0 = HID; sb.split = 16;
        sb.a1 = g_h2[prev]; sb.lda1 = HID;
        Src sa;                               // A(t+1): h1_t only
        sa.a0 = g_h1[cur]; sa.lda0 = HID; sa.split = 16;
        sa.a1 = g_h1[cur]; sa.lda1 = HID;
        const bool doA = (t + 1 < T_STEPS);

        // cold start (post-sync); overlap with out projection
        issue_sub(sb, 0, rowA, coff, pstage + wd0, pstage + wd1);
        issue_sub(sb, 1, rowA, coff, pstage + 2048 + wd0, pstage + 2048 + wd1);
        issue_sub(sb, 2, rowA, coff, pstage + 4096 + wd0, pstage + 4096 + wd1);
        if (t > 0) out_calc(t - 1, g_h2[prev], Wlin, blin, out, ct);

        // ---- B(t): 32 k32 chunks; tail issues A(t+1) chunks 0,1,2 ----
        zero_acc(acc);
        #pragma unroll 2
        for (int j = 0; j < 32; j++) {
            CPA_WAIT2();
            PBAR(mg);
            const uint32_t stg = pstage + (uint32_t)(j & 3) * 2048u;
            load_frags(f, stg, a_off, smu + SM_W2, j * 2, bo_sw);
            const uint32_t ds = pstage + (uint32_t)((j + 3) & 3) * 2048u;
            if (j + 3 < 32)
                issue_sub(sb, j + 3, rowA, coff, ds + wd0, ds + wd1);
            else if (doA)
                issue_sub(sa, j - 29, rowA, coff, ds + wd0, ds + wd1);
            else
                CPA_COMMIT();
            mma_frags(f, acc);
        }
        // gx prefetch for A(t+1) — latency hidden under the epilogue
        uint4 gxv[4];
        if (doA) {
            const uint4* gp = gx_ptr(t + 1);
            #pragma unroll
            for (int k = 0; k < 4; k++) gxv[k] = __ldcg(gp + k);
        }
        epilogue(acc, b2r, g_c2, g_h2[cur], base_row, colb);

        // ---- A(t+1): 16 k32 chunks, acc preloaded with gx ----
        if (doA) {
            init_from_gx(gxv);
            #pragma unroll 2
            for (int j = 0; j < 16; j++) {
                CPA_WAIT2();
                PBAR(mg);
                const uint32_t stg = pstage + (uint32_t)(j & 3) * 2048u;
                load_frags(f, stg, a_off, smu + SM_W1, j * 2, bo_sw);
                if (j + 3 < 16) {
                    const uint32_t ds = pstage + (uint32_t)((j + 3) & 3) * 2048u;
                    issue_sub(sa, j + 3, rowA, coff, ds + wd0, ds + wd1);
                } else CPA_COMMIT();
                mma_frags(f, acc);
            }
            epilogue(acc, b1r, g_c1, g_h1[prev], base_row, colb);   // h1_{t+1}
        }
        group_sync(mt, ++round);
    }
    out_calc(T_STEPS - 1, g_h2[0], Wlin, blin, out, ct);
}

// --------------------------------- launcher ----------------------------------
extern "C" void kernel_launch(void* const* d_in, const int* in_sizes, int n_in,
                              void* d_out, int out_size) {
    const float* signal = (const float*)d_in[0];
    const float* Wih1   = (const float*)d_in[1];
    const float* Whh1   = (const float*)d_in[2];
    const float* bih1   = (const float*)d_in[3];
    const float* bhh1   = (const float*)d_in[4];
    const float* Wih2   = (const float*)d_in[5];
    const float* Whh2   = (const float*)d_in[6];
    const float* bih2   = (const float*)d_in[7];
    const float* bhh2   = (const float*)d_in[8];
    const float* Wlin   = (const float*)d_in[9];
    const float* blin   = (const float*)d_in[10];
    float* out = (float*)d_out;

    (void)in_sizes; (void)n_in; (void)out_size;

    cudaFuncSetAttribute(lstm_persistent,
                         cudaFuncAttributeMaxDynamicSharedMemorySize, SMEM_BYTES);
    cudaFuncSetAttribute(gemm_x_kernel,
                         cudaFuncAttributeMaxDynamicSharedMemorySize, GX_SMEM);

    prep_kernel<<<4096, 256>>>(signal, Wih1, Whh1, bih1, bhh1,
                               Wih2, Whh2, bih2, bhh2);
    gemm_x_kernel<<<NCTA, NTHREADS, GX_SMEM>>>();
    lstm_persistent<<<NCTA, NTHREADS, SMEM_BYTES>>>(Wlin, blin, out);
}

// round 15
// speedup vs baseline: 1.9100x; 1.0356x over previous
#include <cuda_runtime.h>
#include <cuda_fp16.h>
#include <cstdint>

#define T_STEPS 512
#define BATCH   512
#define FEAT    128
#define HID     512
#define TAGS    2
#define NG      2048          // 4*HID
#define K1      640           // FEAT + HID
#define K2      1024          // HID + HID
#define NCTA    128
#define MT      128
#define NT      64
#define NTHREADS 256          // 8 warps: 4 M-subgroups x 2 N-halves, tile 32x32
#define NTGROUP 32            // CTAs per M-group

// resident weights: per k64 block = 64 rows(N) x 128B = 8192 B
#define W1_BLKS 8             // h1 part only (orig k-blocks 2..9)
#define W2_BLKS 16
#define SM_W1   0
#define SM_W2   (W1_BLKS * 8192)                  // 65536
#define SM_AST  ((W1_BLKS + W2_BLKS) * 8192)      // 196608
#define SMEM_BYTES (SM_AST + 4 * 2 * 4096)        // 229376: 4 pairs x 2 k64 slots

// gemm_x kernel smem
#define GX_W    0                                  // 2 blocks = 16384
#define GX_AST  16384
#define GX_SMEM (16384 + 32768)                    // 49152

// ------------------------- device globals (scratch) -------------------------
__device__ __half g_Wp1h[NG * K1];       // permuted [n][k], fp16
__device__ __half g_Wp2h[NG * K2];
__device__ float  g_b1[NG];
__device__ float  g_b2[NG];
__device__ __half g_sigh[T_STEPS * BATCH * FEAT];
__device__ __half g_h1[2][BATCH * HID];
__device__ __half g_h2[2][BATCH * HID];
__device__ float  g_c1[BATCH * HID];
__device__ float  g_c2[BATCH * HID];
__device__ unsigned g_bar4[4];
__device__ unsigned g_gen4[4];
// precomputed x*W1x^T in per-thread fragment order: [ct][t][tid][32 halves]
__device__ __half g_gx[(size_t)NCTA * T_STEPS * NTHREADS * 32];

// ------------------------------- helpers ------------------------------------
__device__ __forceinline__ float sigm(float x) { return 1.0f / (1.0f + __expf(-x)); }
__device__ __forceinline__ void cp16(uint32_t dst, const void* src) {
    asm volatile("cp.async.cg.shared.global [%0], [%1], 16;\n" :: "r"(dst), "l"(src));
}
#define CPA_COMMIT() asm volatile("cp.async.commit_group;\n")
#define CPA_WAIT1()  asm volatile("cp.async.wait_group 1;\n")
#define CPA_WAIT2()  asm volatile("cp.async.wait_group 2;\n")
#define CPA_WAIT0()  asm volatile("cp.async.wait_group 0;\n")
#define PBAR(mg)     asm volatile("bar.sync %0, 64;" :: "r"(1 + (mg)) : "memory")
#define LDSM4(r0, r1, r2, r3, addr)                                            \
    asm volatile("ldmatrix.sync.aligned.m8n8.x4.shared.b16 {%0,%1,%2,%3}, [%4];" \
        : "=r"(r0), "=r"(r1), "=r"(r2), "=r"(r3) : "r"(addr))

__device__ __forceinline__ unsigned ld_acq(const unsigned* p) {
    unsigned v;
    asm volatile("ld.acquire.gpu.u32 %0, [%1];" : "=r"(v) : "l"(p) : "memory");
    return v;
}

// permuted column index n -> original gate row (gate-interleave of 8)
__device__ __forceinline__ int orig_row(long n) {
    int chunk = (int)(n >> 5), w = (int)(n & 31);
    int q = w >> 3, r = w & 7;
    return q * HID + chunk * 8 + r;
}

// ------------------------------ prep kernel ---------------------------------
__global__ void prep_kernel(const float* __restrict__ signal,
                            const float* __restrict__ Wih1, const float* __restrict__ Whh1,
                            const float* __restrict__ bih1, const float* __restrict__ bhh1,
                            const float* __restrict__ Wih2, const float* __restrict__ Whh2,
                            const float* __restrict__ bih2, const float* __restrict__ bhh2) {
    const long NW1 = (long)NG * K1;
    const long NW2 = (long)NG * K2;
    const long NSIG = (long)T_STEPS * BATCH * FEAT;
    const long NH   = (long)BATCH * HID;
    const long TOT = NW1 + NW2 + 2L * NG + NSIG + 6L * NH;
    for (long i = blockIdx.x * (long)blockDim.x + threadIdx.x; i < TOT;
         i += (long)gridDim.x * blockDim.x) {
        if (i < NW1) {
            long n = i / K1, k = i % K1;
            int o = orig_row(n);
            float v = (k < FEAT) ? Wih1[(long)o * FEAT + k]
                                 : Whh1[(long)o * HID + (k - FEAT)];
            g_Wp1h[i] = __float2half_rn(v);
        } else if (i < NW1 + NW2) {
            long j = i - NW1;
            long n = j / K2, k = j % K2;
            int o = orig_row(n);
            float v = (k < HID) ? Wih2[(long)o * HID + k]
                                : Whh2[(long)o * HID + (k - HID)];
            g_Wp2h[j] = __float2half_rn(v);
        } else if (i < NW1 + NW2 + NG) {
            long n = i - NW1 - NW2;
            int o = orig_row(n);
            g_b1[n] = bih1[o] + bhh1[o];
        } else if (i < NW1 + NW2 + 2L * NG) {
            long n = i - NW1 - NW2 - NG;
            int o = orig_row(n);
            g_b2[n] = bih2[o] + bhh2[o];
        } else if (i < NW1 + NW2 + 2L * NG + NSIG) {
            long j = i - NW1 - NW2 - 2L * NG;
            g_sigh[j] = __float2half_rn(signal[j]);
        } else {
            long j = i - (NW1 + NW2 + 2L * NG + NSIG);
            long seg = j / NH, o = j % NH;
            if      (seg == 0) g_h1[0][o] = __float2half_rn(0.f);
            else if (seg == 1) g_h1[1][o] = __float2half_rn(0.f);
            else if (seg == 2) g_h2[0][o] = __float2half_rn(0.f);
            else if (seg == 3) g_h2[1][o] = __float2half_rn(0.f);
            else if (seg == 4) g_c1[o]    = 0.f;
            else               g_c2[o]    = 0.f;
        }
    }
    if (blockIdx.x == 0 && threadIdx.x < 4) {
        g_bar4[threadIdx.x] = 0u;
        g_gen4[threadIdx.x] = 0u;
    }
}

// --------------------- per-M-group barrier (32 CTAs) -------------------------
__device__ __forceinline__ void group_sync(int mt, unsigned target) {
    __syncthreads();
    if (threadIdx.x == 0) {
        __threadfence();
        unsigned a = atomicAdd(&g_bar4[mt], 1u);
        if (a == NTGROUP - 1u) {
            atomicExch(&g_bar4[mt], 0u);
            __threadfence();
            atomicAdd(&g_gen4[mt], 1u);
        } else {
            while (ld_acq(&g_gen4[mt]) < target) { }
        }
        __threadfence();
    }
    __syncthreads();
}

// --------------------------- pair A staging (k64) ----------------------------
struct Src {
    const __half* a0; int lda0; int split;   // k64 chunk idx < split -> a0
    const __half* a1; int lda1;              // otherwise a1
};

// pair-cooperative: 64 threads fill one 4KB slot (32 rows x 128B); 1 commit
__device__ __forceinline__ void issue_k64(const Src& s, int idx, int rowA, int coff,
                                          uint32_t slot, const uint32_t wdj[4]) {
    const __half* p;
    if (idx < s.split) p = s.a0 + (size_t)rowA * s.lda0 + idx * 64 + coff;
    else               p = s.a1 + (size_t)rowA * s.lda1 + (idx - s.split) * 64 + coff;
    #pragma unroll
    for (int j = 0; j < 4; j++) cp16(slot + wdj[j], p + j * 8);
    CPA_COMMIT();
}

// ------------------------ k64 fragment load / MMA ----------------------------
struct F64 { unsigned a[4][2][4]; unsigned b[4][2][4]; };   // [kk][mi|p2][4]

__device__ __forceinline__ void load_k64(F64& f, uint32_t stg,
                                         const uint32_t a_off[2][4],
                                         uint32_t wblk, const uint32_t bo_sw[2][4]) {
    #pragma unroll
    for (int kk = 0; kk < 4; kk++) {
        #pragma unroll
        for (int mi = 0; mi < 2; mi++)
            LDSM4(f.a[kk][mi][0], f.a[kk][mi][1], f.a[kk][mi][2], f.a[kk][mi][3],
                  stg + a_off[mi][kk]);
        #pragma unroll
        for (int p2 = 0; p2 < 2; p2++)
            LDSM4(f.b[kk][p2][0], f.b[kk][p2][1], f.b[kk][p2][2], f.b[kk][p2][3],
                  wblk + bo_sw[p2][kk]);
    }
}

__device__ __forceinline__ void mma_k64(const F64& f, float acc[2][4][4]) {
    #pragma unroll
    for (int kk = 0; kk < 4; kk++)
        #pragma unroll
        for (int mi = 0; mi < 2; mi++)
            #pragma unroll
            for (int j = 0; j < 4; j++) {
                const int p2 = j >> 1, hi = (j & 1) * 2;
                asm volatile(
                    "mma.sync.aligned.m16n8k16.row.col.f32.f16.f16.f32 "
                    "{%0,%1,%2,%3}, {%4,%5,%6,%7}, {%8,%9}, {%0,%1,%2,%3};\n"
                    : "+f"(acc[mi][j][0]), "+f"(acc[mi][j][1]),
                      "+f"(acc[mi][j][2]), "+f"(acc[mi][j][3])
                    : "r"(f.a[kk][mi][0]), "r"(f.a[kk][mi][1]),
                      "r"(f.a[kk][mi][2]), "r"(f.a[kk][mi][3]),
                      "r"(f.b[kk][p2][hi]), "r"(f.b[kk][p2][hi + 1]));
            }
}

__device__ __forceinline__ void zero_acc(float acc[2][4][4]) {
    #pragma unroll
    for (int mi = 0; mi < 2; mi++)
        #pragma unroll
        for (int j = 0; j < 4; j++)
            #pragma unroll
            for (int r = 0; r < 4; r++) acc[mi][j][r] = 0.f;
}

// ------------- register-local LSTM epilogue (c preloaded in regs) -----------
__device__ __forceinline__ void epilogue(const float acc[2][4][4],
                                         const float br[4][2],
                                         const float2 cv[2][2],
                                         float* __restrict__ cbuf,
                                         __half* __restrict__ hout,
                                         int base_row, int colb) {
    #pragma unroll
    for (int mi = 0; mi < 2; mi++) {
        #pragma unroll
        for (int rp = 0; rp < 2; rp++) {
            const int row = base_row + mi * 16 + rp * 8;
            float2 c2 = cv[mi][rp];
            float hv[2];
            #pragma unroll
            for (int b = 0; b < 2; b++) {
                const int rg = rp * 2 + b;
                float gi = acc[mi][0][rg] + br[0][b];
                float gf = acc[mi][1][rg] + br[1][b];
                float gg = acc[mi][2][rg] + br[2][b];
                float go = acc[mi][3][rg] + br[3][b];
                float c  = b ? c2.y : c2.x;
                float cn = sigm(gf) * c + sigm(gi) * tanhf(gg);
                if (b) c2.y = cn; else c2.x = cn;
                hv[b] = sigm(go) * tanhf(cn);
            }
            *(float2*)(cbuf + (size_t)row * HID + colb) = c2;
            *(__half2*)(hout + (size_t)row * HID + colb) =
                __floats2half2_rn(hv[0], hv[1]);
        }
    }
}

// ----------------------------- output projection -----------------------------
__device__ __forceinline__ void out_calc(int tp, const __half* __restrict__ h2cur,
                                         const float* __restrict__ Wlin,
                                         const float* __restrict__ blin,
                                         float* __restrict__ out, int ct) {
    const int tid = threadIdx.x, lane = tid & 31, wid = tid >> 5;
    if (wid >= 4) return;
    const int b = ct * 4 + wid;
    const __half* hrow = h2cur + (size_t)b * HID;
    float s0 = 0.f, s1 = 0.f;
    #pragma unroll 8
    for (int k = lane; k < HID; k += 32) {
        float hv = __half2float(__ldcg(hrow + k));
        s0 += hv * __ldg(Wlin + k);
        s1 += hv * __ldg(Wlin + HID + k);
    }
    #pragma unroll
    for (int o = 16; o; o >>= 1) {
        s0 += __shfl_xor_sync(0xffffffffu, s0, o);
        s1 += __shfl_xor_sync(0xffffffffu, s1, o);
    }
    if (lane == 0) {
        out[(size_t)b * (T_STEPS * TAGS) + tp * TAGS + 0] = s0 + blin[0];
        out[(size_t)b * (T_STEPS * TAGS) + tp * TAGS + 1] = s1 + blin[1];
    }
}

// ======================= gemm_x: gx = x_t * W1x^T for all t ==================
__global__ void __launch_bounds__(NTHREADS, 1)
gemm_x_kernel() {
    extern __shared__ char smc[];
    const uint32_t smu = (uint32_t)__cvta_generic_to_shared(smc);
    const int tid = threadIdx.x, w = tid >> 5, lane = tid & 31;
    const int mg = w >> 1, nh = w & 1;
    const int ct = blockIdx.x;
    const int mt = ct >> 5, nt = ct & 31;
    const int m0 = mt * MT, n0 = nt * NT;

    // preload W1x (k blocks 0,1 of g_Wp1h)
    {
        int row = tid >> 2, part = tid & 3;
        uint32_t rb = (uint32_t)(row * 128 + part * 32);
        uint32_t o0 = rb;        o0 ^= (o0 >> 3) & 0x70u;
        uint32_t o1 = rb + 16;   o1 ^= (o1 >> 3) & 0x70u;
        const __half* s1 = g_Wp1h + (size_t)(n0 + row) * K1 + part * 16;
        for (int ckk = 0; ckk < 2; ckk++) {
            cp16(smu + GX_W + ckk * 8192 + o0, s1 + ckk * 64);
            cp16(smu + GX_W + ckk * 8192 + o1, s1 + ckk * 64 + 8);
        }
        CPA_COMMIT();
        CPA_WAIT0();
        __syncthreads();
    }

    const uint32_t b_off0 = (uint32_t)(((((lane >> 4) & 1) * 8 + (lane & 7)) * 128)
                                       + ((lane >> 3) & 1) * 16);
    uint32_t bo_sw[2][4];
    #pragma unroll
    for (int p2 = 0; p2 < 2; p2++)
        #pragma unroll
        for (int kk = 0; kk < 4; kk++) {
            uint32_t bo = b_off0 + (uint32_t)((2 * nh + p2) * 2048 + kk * 32);
            bo ^= (bo >> 3) & 0x70u;
            bo_sw[p2][kk] = bo;
        }

    const uint32_t pstage = smu + GX_AST + (uint32_t)mg * 8192u;
    const int pt = nh * 32 + lane;
    const uint32_t wpre = (uint32_t)((pt >> 2) * 128 + ((pt >> 1) & 1) * 64
                                     + (pt & 1) * 32);
    const uint32_t wsw  = ((uint32_t)(pt >> 2) & 7u) << 4;
    const uint32_t wd0  = wpre ^ wsw;
    const uint32_t wd1  = (wpre + 16) ^ wsw;
    const int coff = (lane & 1) * 16;
    const int rowm = m0 + mg * 32 + nh * 16 + (lane >> 1);

    const int rr = lane & 15;
    uint32_t a_off2[2][2];
    #pragma unroll
    for (int mi = 0; mi < 2; mi++)
        #pragma unroll
        for (int kk = 0; kk < 2; kk++) {
            uint32_t ap = (uint32_t)(mi * 1024 + (rr >> 1) * 128 + (rr & 1) * 64
                                     + kk * 32 + (lane >> 4) * 16);
            ap ^= ((uint32_t)(rr >> 1) & 7u) << 4;
            a_off2[mi][kk] = ap;
        }

    auto issue_x = [&](int c) {
        const int t = c >> 2, s = c & 3;
        const __half* p = g_sigh + ((size_t)t * BATCH + rowm) * FEAT + s * 32 + coff;
        const uint32_t stg = pstage + (uint32_t)(c & 3) * 2048u;
        cp16(stg + wd0, p);
        cp16(stg + wd1, p + 8);
        CPA_COMMIT();
    };

    float acc[2][4][4];
    issue_x(0); issue_x(1); issue_x(2);
    zero_acc(acc);
    const int NCH = 4 * T_STEPS;
    for (int c = 0; c < NCH; c++) {
        CPA_WAIT2();
        PBAR(mg);
        const uint32_t stg = pstage + (uint32_t)(c & 3) * 2048u;
        // per-k32 frag load + mma (2 k16)
        #pragma unroll
        for (int kk = 0; kk < 2; kk++) {
            unsigned a[2][4], b[2][4];
            #pragma unroll
            for (int mi = 0; mi < 2; mi++)
                LDSM4(a[mi][0], a[mi][1], a[mi][2], a[mi][3], stg + a_off2[mi][kk]);
            const int kg = (c & 3) * 2 + kk;
            const uint32_t wblk = smu + GX_W + (uint32_t)(kg >> 2) * 8192u;
            const int k4 = kg & 3;
            #pragma unroll
            for (int p2 = 0; p2 < 2; p2++)
                LDSM4(b[p2][0], b[p2][1], b[p2][2], b[p2][3], wblk + bo_sw[p2][k4]);
            if (kk == 0) { if (c + 3 < NCH) issue_x(c + 3); else CPA_COMMIT(); }
            #pragma unroll
            for (int mi = 0; mi < 2; mi++)
                #pragma unroll
                for (int j = 0; j < 4; j++) {
                    const int p2 = j >> 1, hi = (j & 1) * 2;
                    asm volatile(
                        "mma.sync.aligned.m16n8k16.row.col.f32.f16.f16.f32 "
                        "{%0,%1,%2,%3}, {%4,%5,%6,%7}, {%8,%9}, {%0,%1,%2,%3};\n"
                        : "+f"(acc[mi][j][0]), "+f"(acc[mi][j][1]),
                          "+f"(acc[mi][j][2]), "+f"(acc[mi][j][3])
                        : "r"(a[mi][0]), "r"(a[mi][1]), "r"(a[mi][2]), "r"(a[mi][3]),
                          "r"(b[p2][hi]), "r"(b[p2][hi + 1]));
                }
        }
        if ((c & 3) == 3) {
            const int t = c >> 2;
            uint4 v[4];
            __half2* hp = (__half2*)v;
            #pragma unroll
            for (int mi = 0; mi < 2; mi++)
                #pragma unroll
                for (int j = 0; j < 4; j++)
                    #pragma unroll
                    for (int r = 0; r < 4; r += 2)
                        hp[((mi * 4 + j) * 4 + r) >> 1] =
                            __floats2half2_rn(acc[mi][j][r], acc[mi][j][r + 1]);
            __half* dst = g_gx + ((size_t)(ct * T_STEPS + t) * NTHREADS + tid) * 32;
            #pragma unroll
            for (int k = 0; k < 4; k++) *((uint4*)(dst + k * 8)) = v[k];
            zero_acc(acc);
        }
    }
}

// ------------------------------ persistent kernel ----------------------------
__global__ void __launch_bounds__(NTHREADS, 1)
lstm_persistent(const float* __restrict__ Wlin, const float* __restrict__ blin,
                float* __restrict__ out) {
    extern __shared__ char smc[];
    const uint32_t smu = (uint32_t)__cvta_generic_to_shared(smc);
    const int tid = threadIdx.x, w = tid >> 5, lane = tid & 31;
    const int mg = w >> 1, nh = w & 1;
    const int ct = blockIdx.x;
    const int mt = ct >> 5, nt = ct & 31;
    const int m0 = mt * MT, n0 = nt * NT, H0 = nt * 16;

    // ---- preload resident W1h (8 blocks: orig k-blocks 2..9) + W2 (16) ----
    {
        int row = tid >> 2, part = tid & 3;
        uint32_t rb = (uint32_t)(row * 128 + part * 32);
        uint32_t o0 = rb;        o0 ^= (o0 >> 3) & 0x70u;
        uint32_t o1 = rb + 16;   o1 ^= (o1 >> 3) & 0x70u;
        const __half* s1 = g_Wp1h + (size_t)(n0 + row) * K1 + part * 16;
        for (int ckk = 0; ckk < W1_BLKS; ckk++) {
            cp16(smu + SM_W1 + ckk * 8192 + o0, s1 + (ckk + 2) * 64);
            cp16(smu + SM_W1 + ckk * 8192 + o1, s1 + (ckk + 2) * 64 + 8);
        }
        const __half* s2 = g_Wp2h + (size_t)(n0 + row) * K2 + part * 16;
        for (int ckk = 0; ckk < W2_BLKS; ckk++) {
            cp16(smu + SM_W2 + ckk * 8192 + o0, s2 + ckk * 64);
            cp16(smu + SM_W2 + ckk * 8192 + o1, s2 + ckk * 64 + 8);
        }
        CPA_COMMIT();
        CPA_WAIT0();
        __syncthreads();
    }

    // ---- per-thread biases in registers (gate g, sub-col b) ----
    float b1r[4][2], b2r[4][2];
    #pragma unroll
    for (int g = 0; g < 4; g++)
        #pragma unroll
        for (int b = 0; b < 2; b++) {
            int c = n0 + nh * 32 + g * 8 + 2 * (lane & 3) + b;
            b1r[g][b] = g_b1[c];
            b2r[g][b] = g_b2[c];
        }

    // ---- swizzled LDSM offsets for B: this warp's two n16 blocks ----
    const uint32_t b_off0 = (uint32_t)(((((lane >> 4) & 1) * 8 + (lane & 7)) * 128)
                                       + ((lane >> 3) & 1) * 16);
    uint32_t bo_sw[2][4];
    #pragma unroll
    for (int p2 = 0; p2 < 2; p2++)
        #pragma unroll
        for (int kk = 0; kk < 4; kk++) {
            uint32_t bo = b_off0 + (uint32_t)((2 * nh + p2) * 2048 + kk * 32);
            bo ^= (bo >> 3) & 0x70u;
            bo_sw[p2][kk] = bo;
        }

    // ---- pair A stage: 2 slots x 4KB (k64: 32 rows x 128B) ----
    const uint32_t pstage = smu + SM_AST + (uint32_t)mg * 8192u;
    const int pt = nh * 32 + lane;
    uint32_t wdj[4];
    {
        const uint32_t wpre = (uint32_t)((pt >> 1) * 128 + (pt & 1) * 64);
        const uint32_t xr   = ((uint32_t)(pt >> 1) & 7u) << 4;
        #pragma unroll
        for (int j = 0; j < 4; j++) wdj[j] = (wpre + j * 16) ^ xr;
    }
    const int coff = (pt & 1) * 32;                 // halves
    const int rowA = m0 + mg * 32 + (pt >> 1);

    // ---- LDSM A read offsets [mi][kk] (kk = k16 within k64) ----
    const int rr = lane & 15;
    uint32_t a_off[2][4];
    #pragma unroll
    for (int mi = 0; mi < 2; mi++)
        #pragma unroll
        for (int kk = 0; kk < 4; kk++) {
            int row = mi * 16 + rr;
            uint32_t col = (uint32_t)(kk * 32 + (lane >> 4) * 16);
            a_off[mi][kk] = (uint32_t)(row * 128) + (col ^ ((uint32_t)(row & 7) << 4));
        }

    const int base_row = m0 + mg * 32 + (lane >> 2);
    const int colb = H0 + nh * 8 + 2 * (lane & 3);

    float acc[2][4][4];
    F64 f;
    unsigned round = 0;

    auto init_from_gx = [&](const uint4 gxv[4]) {
        const __half2* hp = (const __half2*)gxv;
        #pragma unroll
        for (int mi = 0; mi < 2; mi++)
            #pragma unroll
            for (int j = 0; j < 4; j++)
                #pragma unroll
                for (int r = 0; r < 4; r += 2) {
                    float2 f2 = __half22float2(hp[((mi * 4 + j) * 4 + r) >> 1]);
                    acc[mi][j][r]     = f2.x;
                    acc[mi][j][r + 1] = f2.y;
                }
    };
    auto gx_ptr = [&](int t) {
        return (const uint4*)(g_gx + ((size_t)(ct * T_STEPS + t) * NTHREADS + tid) * 32);
    };
    auto preload_c = [&](const float* cbuf, float2 cv[2][2]) {
        #pragma unroll
        for (int mi = 0; mi < 2; mi++)
            #pragma unroll
            for (int rp = 0; rp < 2; rp++)
                cv[mi][rp] = *(const float2*)(cbuf
                    + (size_t)(base_row + mi * 16 + rp * 8) * HID + colb);
    };

    // ---------------- prologue: A(0) = gx(0) + 0*W1h -> h1_0 in g_h1[1] ------
    {
        Src sa;
        sa.a0 = g_h1[0]; sa.lda0 = HID; sa.split = 8;     // zeros
        sa.a1 = g_h1[0]; sa.lda1 = HID;
        issue_k64(sa, 0, rowA, coff, pstage, wdj);
        issue_k64(sa, 1, rowA, coff, pstage + 4096u, wdj);
        uint4 gxv[4];
        const uint4* gp = gx_ptr(0);
        #pragma unroll
        for (int k = 0; k < 4; k++) gxv[k] = __ldcg(gp + k);
        float2 cvA[2][2];
        preload_c(g_c1, cvA);
        init_from_gx(gxv);
        for (int j = 0; j < 8; j++) {
            if (j + 1 < 8) CPA_WAIT1(); else CPA_WAIT0();
            PBAR(mg);
            const uint32_t stg = pstage + (uint32_t)(j & 1) * 4096u;
            load_k64(f, stg, a_off, smu + SM_W1 + (uint32_t)j * 8192u, bo_sw);
            if (j + 2 < 8) issue_k64(sa, j + 2, rowA, coff, stg, wdj);
            else           CPA_COMMIT();
            mma_k64(f, acc);
        }
        epilogue(acc, b1r, cvA, g_c1, g_h1[1], base_row, colb);
        group_sync(mt, ++round);
    }

    // ------------- steady state: region_t = [ B(t) ; A(t+1) ] ----------------
    for (int t = 0; t < T_STEPS; t++) {
        const int cur = (t + 1) & 1, prev = t & 1;
        Src sb;                               // B(t): [h1_t , h2_{t-1}]
        sb.a0 = g_h1[cur]; sb.lda0 = HID; sb.split = 8;
        sb.a1 = g_h2[prev]; sb.lda1 = HID;
        Src sa;                               // A(t+1): h1_t only (x via gx)
        sa.a0 = g_h1[cur]; sa.lda0 = HID; sa.split = 8;
        sa.a1 = g_h1[cur]; sa.lda1 = HID;
        const bool doA = (t + 1 < T_STEPS);

        // cold start (post-sync); overlap with out projection + preloads
        issue_k64(sb, 0, rowA, coff, pstage, wdj);
        issue_k64(sb, 1, rowA, coff, pstage + 4096u, wdj);
        if (t > 0) out_calc(t - 1, g_h2[prev], Wlin, blin, out, ct);
        float2 cvB[2][2], cvA[2][2];
        preload_c(g_c2, cvB);
        preload_c(g_c1, cvA);
        uint4 gxv[4];
        if (doA) {
            const uint4* gp = gx_ptr(t + 1);
            #pragma unroll
            for (int k = 0; k < 4; k++) gxv[k] = __ldcg(gp + k);
        }

        // ---- B(t): 16 k64 chunks; tail issues A(t+1) chunks 0,1 ----
        zero_acc(acc);
        for (int j = 0; j < 16; j++) {
            CPA_WAIT1();
            PBAR(mg);
            const uint32_t stg = pstage + (uint32_t)(j & 1) * 4096u;
            load_k64(f, stg, a_off, smu + SM_W2 + (uint32_t)j * 8192u, bo_sw);
            if (j + 2 < 16)
                issue_k64(sb, j + 2, rowA, coff, stg, wdj);
            else if (doA)
                issue_k64(sa, j - 14, rowA, coff, stg, wdj);
            else
                CPA_COMMIT();
            mma_k64(f, acc);
        }
        epilogue(acc, b2r, cvB, g_c2, g_h2[cur], base_row, colb);

        // ---- A(t+1): 8 k64 chunks, acc preloaded with gx ----
        if (doA) {
            init_from_gx(gxv);
            for (int j = 0; j < 8; j++) {
                if (j + 1 < 8) CPA_WAIT1(); else CPA_WAIT0();
                PBAR(mg);
                const uint32_t stg = pstage + (uint32_t)(j & 1) * 4096u;
                load_k64(f, stg, a_off, smu + SM_W1 + (uint32_t)j * 8192u, bo_sw);
                if (j + 2 < 8) issue_k64(sa, j + 2, rowA, coff, stg, wdj);
                else           CPA_COMMIT();
                mma_k64(f, acc);
            }
            epilogue(acc, b1r, cvA, g_c1, g_h1[prev], base_row, colb);  // h1_{t+1}
        }
        group_sync(mt, ++round);
    }
    out_calc(T_STEPS - 1, g_h2[0], Wlin, blin, out, ct);
}

// --------------------------------- launcher ----------------------------------
extern "C" void kernel_launch(void* const* d_in, const int* in_sizes, int n_in,
                              void* d_out, int out_size) {
    const float* signal = (const float*)d_in[0];
    const float* Wih1   = (const float*)d_in[1];
    const float* Whh1   = (const float*)d_in[2];
    const float* bih1   = (const float*)d_in[3];
    const float* bhh1   = (const float*)d_in[4];
    const float* Wih2   = (const float*)d_in[5];
    const float* Whh2   = (const float*)d_in[6];
    const float* bih2   = (const float*)d_in[7];
    const float* bhh2   = (const float*)d_in[8];
    const float* Wlin   = (const float*)d_in[9];
    const float* blin   = (const float*)d_in[10];
    float* out = (float*)d_out;

    (void)in_sizes; (void)n_in; (void)out_size;

    cudaFuncSetAttribute(lstm_persistent,
                         cudaFuncAttributeMaxDynamicSharedMemorySize, SMEM_BYTES);
    cudaFuncSetAttribute(gemm_x_kernel,
                         cudaFuncAttributeMaxDynamicSharedMemorySize, GX_SMEM);

    prep_kernel<<<4096, 256>>>(signal, Wih1, Whh1, bih1, bhh1,
                               Wih2, Whh2, bih2, bhh2);
    gemm_x_kernel<<<NCTA, NTHREADS, GX_SMEM>>>();
    lstm_persistent<<<NCTA, NTHREADS, SMEM_BYTES>>>(Wlin, blin, out);
}